// round 1
// baseline (speedup 1.0000x reference)
#include <cuda_runtime.h>
#include <math.h>

// Problem constants
#define B_SZ 4
#define T_SZ 2048
#define D_SZ 1024
#define M_SZ (B_SZ * T_SZ)          // 8192 rows for row-flattened GEMMs
#define ETA_C 0.1f
#define LCA_GEMM_ITERS 9            // iteration 1 is pure elementwise (a=0, v=0)

// ---------------- scratch (static device globals; no allocation) -------------
__device__ float g_uq[M_SZ * D_SZ];        // u for q-LCA
__device__ float g_uk[M_SZ * D_SZ];        // u for k-LCA
__device__ float g_vv[M_SZ * D_SZ];        // attention "values" v
__device__ float g_vq[M_SZ * D_SZ];        // LCA state v (q)
__device__ float g_vk[M_SZ * D_SZ];        // LCA state v (k)
__device__ float g_aq[2][M_SZ * D_SZ];     // LCA code a (q), ping-pong
__device__ float g_ak[2][M_SZ * D_SZ];     // LCA code a (k), ping-pong
__device__ float g_Gq[D_SZ * D_SZ];        // symmetrized zero-diag G (q)
__device__ float g_Gk[D_SZ * D_SZ];        // symmetrized zero-diag G (k)
__device__ float g_S[(size_t)B_SZ * T_SZ * T_SZ];   // scores / attn probs
__device__ float g_o[M_SZ * D_SZ];         // attention output

// ---------------- GEMM config ------------------------------------------------
#define BM 128
#define BN 128
#define BKK 8
#define TM 8
#define TN 8
#define NTHR 256

// Epilogue modes for the NT GEMM (C[m,n] = sum_k A[m,k]*B[n,k])
#define MODE_PLAIN 0   // C = alpha * acc
#define MODE_LCA   1   // fused LCA prox update: reads U, V-state, loglam; writes V and C(=a_next)
#define MODE_SCORE 2   // plain + skip blocks entirely above the causal diagonal

template <int MODE>
__global__ void __launch_bounds__(NTHR, 2)
gemm_nt(const float* __restrict__ A, const float* __restrict__ Bm,
        float* __restrict__ C, int M, int N, int K, float alpha,
        long sA, long sB, long sC,
        const float* __restrict__ U, float* __restrict__ Vst,
        const float* __restrict__ loglam)
{
    const int r0 = blockIdx.y * BM;
    const int c0 = blockIdx.x * BN;
    if (MODE == MODE_SCORE && c0 >= r0 + BM) return;   // fully causal-masked tile

    const long bz = blockIdx.z;
    A  += bz * sA;
    Bm += bz * sB;
    C  += bz * sC;

    __shared__ float As[BKK][BM];
    __shared__ float Bs[BKK][BN];

    const int tid = threadIdx.x;
    const int tr = tid / 16;            // 0..15 (row group)
    const int tc = tid % 16;            // 0..15 (col group)
    const int lr  = tid / 2;            // 0..127 load row
    const int lc4 = (tid % 2) * 4;      // 0 or 4  load col (float4)

    float acc[TM][TN];
#pragma unroll
    for (int i = 0; i < TM; i++)
#pragma unroll
        for (int j = 0; j < TN; j++) acc[i][j] = 0.f;

    const float* Aptr = A  + (long)(r0 + lr) * K + lc4;
    const float* Bptr = Bm + (long)(c0 + lr) * K + lc4;

    for (int k0 = 0; k0 < K; k0 += BKK) {
        float4 av = *(const float4*)(Aptr + k0);
        float4 bv = *(const float4*)(Bptr + k0);
        __syncthreads();
        As[lc4 + 0][lr] = av.x; As[lc4 + 1][lr] = av.y;
        As[lc4 + 2][lr] = av.z; As[lc4 + 3][lr] = av.w;
        Bs[lc4 + 0][lr] = bv.x; Bs[lc4 + 1][lr] = bv.y;
        Bs[lc4 + 2][lr] = bv.z; Bs[lc4 + 3][lr] = bv.w;
        __syncthreads();
#pragma unroll
        for (int kk = 0; kk < BKK; kk++) {
            float a[TM], b[TN];
            *(float4*)&a[0] = *(const float4*)&As[kk][tr * TM];
            *(float4*)&a[4] = *(const float4*)&As[kk][tr * TM + 4];
            *(float4*)&b[0] = *(const float4*)&Bs[kk][tc * TN];
            *(float4*)&b[4] = *(const float4*)&Bs[kk][tc * TN + 4];
#pragma unroll
            for (int i = 0; i < TM; i++)
#pragma unroll
                for (int j = 0; j < TN; j++)
                    acc[i][j] += a[i] * b[j];
        }
    }

    const float lam = (MODE == MODE_LCA) ? expf(*loglam) : 0.f;

#pragma unroll
    for (int i = 0; i < TM; i++) {
        const long m = r0 + tr * TM + i;
        const long base = m * (long)N + c0 + tc * TN;
#pragma unroll
        for (int j = 0; j < TN; j++) {
            const long idx = base + j;
            if (MODE == MODE_LCA) {
                float vold = Vst[idx];
                float vn = vold + ETA_C * (U[idx] - vold - acc[i][j]);
                Vst[idx] = vn;
                float s = fabsf(vn) - lam;
                C[idx] = (s > 0.f) ? copysignf(s, vn) : 0.f;
            } else {
                C[idx] = alpha * acc[i][j];
            }
        }
    }
}

// NN GEMM with causal K-limit: C[m,n] = sum_{k<=m} A[m,k]*B[k,n]
__global__ void __launch_bounds__(NTHR, 2)
gemm_nn_causal(const float* __restrict__ A, const float* __restrict__ Bm,
               float* __restrict__ C, int M, int N, int K,
               long sA, long sB, long sC)
{
    const int r0 = blockIdx.y * BM;
    const int c0 = blockIdx.x * BN;
    const long bz = blockIdx.z;
    A  += bz * sA;
    Bm += bz * sB;
    C  += bz * sC;

    __shared__ float As[BKK][BM];
    __shared__ float Bs[BKK][BN];

    const int tid = threadIdx.x;
    const int tr = tid / 16, tc = tid % 16;
    const int lrA  = tid / 2,  lc4A = (tid % 2) * 4;
    const int lrB  = tid / 32, lc4B = (tid % 32) * 4;

    float acc[TM][TN];
#pragma unroll
    for (int i = 0; i < TM; i++)
#pragma unroll
        for (int j = 0; j < TN; j++) acc[i][j] = 0.f;

    const int kmax = min(K, r0 + BM);   // P[m,k]==0 for k>m

    for (int k0 = 0; k0 < kmax; k0 += BKK) {
        float4 av = *(const float4*)(A  + (long)(r0 + lrA) * K + k0 + lc4A);
        float4 bv = *(const float4*)(Bm + (long)(k0 + lrB) * N + c0 + lc4B);
        __syncthreads();
        As[lc4A + 0][lrA] = av.x; As[lc4A + 1][lrA] = av.y;
        As[lc4A + 2][lrA] = av.z; As[lc4A + 3][lrA] = av.w;
        *(float4*)&Bs[lrB][lc4B] = bv;
        __syncthreads();
#pragma unroll
        for (int kk = 0; kk < BKK; kk++) {
            float a[TM], b[TN];
            *(float4*)&a[0] = *(const float4*)&As[kk][tr * TM];
            *(float4*)&a[4] = *(const float4*)&As[kk][tr * TM + 4];
            *(float4*)&b[0] = *(const float4*)&Bs[kk][tc * TN];
            *(float4*)&b[4] = *(const float4*)&Bs[kk][tc * TN + 4];
#pragma unroll
            for (int i = 0; i < TM; i++)
#pragma unroll
                for (int j = 0; j < TN; j++)
                    acc[i][j] += a[i] * b[j];
        }
    }

#pragma unroll
    for (int i = 0; i < TM; i++) {
        const long base = (long)(r0 + tr * TM + i) * N + c0 + tc * TN;
#pragma unroll
        for (int j = 0; j < TN; j++)
            C[base + j] = acc[i][j];
    }
}

// Gs = 0.5*(G + G^T), zero diagonal
__global__ void symzero(const float* __restrict__ G, float* __restrict__ Gs)
{
    const long idx = (long)blockIdx.x * blockDim.x + threadIdx.x;
    if (idx >= (long)D_SZ * D_SZ) return;
    const int i = (int)(idx / D_SZ), j = (int)(idx % D_SZ);
    Gs[idx] = (i == j) ? 0.f : 0.5f * (G[idx] + G[(long)j * D_SZ + i]);
}

// LCA iteration 1 (v=0, a=0): v = eta*u; a = soft(v, lam)
__global__ void lca_init(const float* __restrict__ U, float* __restrict__ Vst,
                         float* __restrict__ Aout, const float* __restrict__ loglam)
{
    const long idx = (long)blockIdx.x * blockDim.x + threadIdx.x;
    const float lam = expf(*loglam);
    const float vn = ETA_C * U[idx];
    Vst[idx] = vn;
    const float s = fabsf(vn) - lam;
    Aout[idx] = (s > 0.f) ? copysignf(s, vn) : 0.f;
}

// Causal row softmax in-place; zeros the masked tail
__global__ void softmax_causal(float* __restrict__ S)
{
    const int i = blockIdx.x;           // query row
    const int b = blockIdx.y;           // batch
    float* row = S + ((long)b * T_SZ + i) * T_SZ;
    const int tid = threadIdx.x;
    const int n = i + 1;

    __shared__ float red[256];

    float mx = -INFINITY;
    for (int j = tid; j < n; j += 256) mx = fmaxf(mx, row[j]);
    red[tid] = mx;
    __syncthreads();
    for (int s = 128; s > 0; s >>= 1) {
        if (tid < s) red[tid] = fmaxf(red[tid], red[tid + s]);
        __syncthreads();
    }
    mx = red[0];
    __syncthreads();

    float sum = 0.f;
    for (int j = tid; j < n; j += 256) {
        float e = expf(row[j] - mx);
        row[j] = e;
        sum += e;
    }
    red[tid] = sum;
    __syncthreads();
    for (int s = 128; s > 0; s >>= 1) {
        if (tid < s) red[tid] += red[tid + s];
        __syncthreads();
    }
    const float inv = 1.f / red[0];

    for (int j = tid; j < n; j += 256) row[j] *= inv;
    for (int j = n + tid; j < T_SZ; j += 256) row[j] = 0.f;   // masked tail -> 0
}

extern "C" void kernel_launch(void* const* d_in, const int* in_sizes, int n_in,
                              void* d_out, int out_size)
{
    const float* x        = (const float*)d_in[0];
    const float* W_qkv    = (const float*)d_in[1];
    const float* W_out    = (const float*)d_in[2];
    const float* Gq_raw   = (const float*)d_in[3];
    const float* loglam_q = (const float*)d_in[4];
    const float* Gk_raw   = (const float*)d_in[5];
    const float* loglam_k = (const float*)d_in[6];
    float* out = (float*)d_out;
    (void)in_sizes; (void)n_in; (void)out_size;

    float *uq, *uk, *vv, *vq, *vk, *aqb, *akb, *Gq, *Gk, *S, *o;
    cudaGetSymbolAddress((void**)&uq,  g_uq);
    cudaGetSymbolAddress((void**)&uk,  g_uk);
    cudaGetSymbolAddress((void**)&vv,  g_vv);
    cudaGetSymbolAddress((void**)&vq,  g_vq);
    cudaGetSymbolAddress((void**)&vk,  g_vk);
    cudaGetSymbolAddress((void**)&aqb, g_aq);
    cudaGetSymbolAddress((void**)&akb, g_ak);
    cudaGetSymbolAddress((void**)&Gq,  g_Gq);
    cudaGetSymbolAddress((void**)&Gk,  g_Gk);
    cudaGetSymbolAddress((void**)&S,   g_S);
    cudaGetSymbolAddress((void**)&o,   g_o);

    float* aq[2] = { aqb, aqb + (long)M_SZ * D_SZ };
    float* ak[2] = { akb, akb + (long)M_SZ * D_SZ };

    const dim3 thr(NTHR);
    const long MD = (long)M_SZ * D_SZ;

    // 1) symmetrize + zero-diag G
    {
        dim3 g((D_SZ * D_SZ + 255) / 256);
        symzero<<<g, thr>>>(Gq_raw, Gq);
        symzero<<<g, thr>>>(Gk_raw, Gk);
    }

    // 2) QKV projection: u_q, u_k, v  (NT GEMMs, M=8192, N=1024, K=1024)
    {
        dim3 g(D_SZ / BN, M_SZ / BM, 1);
        gemm_nt<MODE_PLAIN><<<g, thr>>>(x, W_qkv,                           uq, M_SZ, D_SZ, D_SZ, 1.f, 0, 0, 0, nullptr, nullptr, nullptr);
        gemm_nt<MODE_PLAIN><<<g, thr>>>(x, W_qkv + (long)D_SZ * D_SZ,       uk, M_SZ, D_SZ, D_SZ, 1.f, 0, 0, 0, nullptr, nullptr, nullptr);
        gemm_nt<MODE_PLAIN><<<g, thr>>>(x, W_qkv + (long)2 * D_SZ * D_SZ,   vv, M_SZ, D_SZ, D_SZ, 1.f, 0, 0, 0, nullptr, nullptr, nullptr);
    }

    // 3) LCA iteration 1 (elementwise)
    {
        dim3 g((unsigned)(MD / 256));
        lca_init<<<g, thr>>>(uq, vq, aq[0], loglam_q);
        lca_init<<<g, thr>>>(uk, vk, ak[0], loglam_k);
    }

    // 4) LCA iterations 2..10: fused a@G GEMM + prox (G symmetric -> NT form)
    {
        dim3 g(D_SZ / BN, M_SZ / BM, 1);
        int cur = 0;
        for (int it = 0; it < LCA_GEMM_ITERS; it++) {
            gemm_nt<MODE_LCA><<<g, thr>>>(aq[cur], Gq, aq[cur ^ 1], M_SZ, D_SZ, D_SZ, 1.f,
                                          0, 0, 0, uq, vq, loglam_q);
            gemm_nt<MODE_LCA><<<g, thr>>>(ak[cur], Gk, ak[cur ^ 1], M_SZ, D_SZ, D_SZ, 1.f,
                                          0, 0, 0, uk, vk, loglam_k);
            cur ^= 1;
        }
        // LCA_GEMM_ITERS = 9 (odd) -> final codes live in buffer 1
    }
    float* qf = aq[1];
    float* kf = ak[1];

    // 5) scores S = q k^T / sqrt(D), causal tiles skipped (batched via grid.z)
    {
        dim3 g(T_SZ / BN, T_SZ / BM, B_SZ);
        gemm_nt<MODE_SCORE><<<g, thr>>>(qf, kf, S, T_SZ, T_SZ, D_SZ, 0.03125f,
                                        (long)T_SZ * D_SZ, (long)T_SZ * D_SZ, (long)T_SZ * T_SZ,
                                        nullptr, nullptr, nullptr);
    }

    // 6) causal softmax (in place, zeros masked tail)
    {
        dim3 g(T_SZ, B_SZ);
        softmax_causal<<<g, thr>>>(S);
    }

    // 7) o = P @ v  (NN GEMM with causal k-limit, batched)
    {
        dim3 g(D_SZ / BN, T_SZ / BM, B_SZ);
        gemm_nn_causal<<<g, thr>>>(S, vv, o, T_SZ, D_SZ, T_SZ,
                                   (long)T_SZ * T_SZ, (long)T_SZ * D_SZ, (long)T_SZ * D_SZ);
    }

    // 8) out = o @ W_out^T
    {
        dim3 g(D_SZ / BN, M_SZ / BM, 1);
        gemm_nt<MODE_PLAIN><<<g, thr>>>(o, W_out, out, M_SZ, D_SZ, D_SZ, 1.f,
                                        0, 0, 0, nullptr, nullptr, nullptr);
    }
}

// round 3
// speedup vs baseline: 3.0218x; 3.0218x over previous
#include <cuda_runtime.h>
#include <cstdint>
#include <math.h>

// ---------------- problem constants ----------------
#define B_SZ 4
#define T_SZ 2048
#define D_SZ 1024
#define M_SZ (B_SZ * T_SZ)
#define ETA_C 0.1f
#define LCA_GEMM_ITERS 9   // iteration 1 is elementwise (a=0, v=0)

// ---------------- scratch (device globals; no allocation) ----------------
__device__ float g_uq[M_SZ * D_SZ];
__device__ float g_uk[M_SZ * D_SZ];
__device__ float g_vv[M_SZ * D_SZ];
__device__ float g_vt[M_SZ * D_SZ];          // V transposed per batch: [B][D][T]
__device__ float g_vq[M_SZ * D_SZ];
__device__ float g_vk[M_SZ * D_SZ];
__device__ float g_aq[2][M_SZ * D_SZ];
__device__ float g_ak[2][M_SZ * D_SZ];
__device__ float g_Gq[D_SZ * D_SZ];
__device__ float g_Gk[D_SZ * D_SZ];
__device__ float g_S[(size_t)B_SZ * T_SZ * T_SZ];
__device__ float g_o[M_SZ * D_SZ];

// ---------------- helpers ----------------
__device__ __forceinline__ uint32_t smem_u32(const void* p) {
    uint32_t a;
    asm("{ .reg .u64 t; cvta.to.shared.u64 t, %1; cvt.u32.u64 %0, t; }" : "=r"(a) : "l"(p));
    return a;
}
__device__ __forceinline__ void cp_async16(uint32_t dst, const void* src) {
    asm volatile("cp.async.cg.shared.global [%0], [%1], 16;" :: "r"(dst), "l"(src));
}
#define CP_COMMIT() asm volatile("cp.async.commit_group;" ::: "memory")
#define CP_WAIT1()  asm volatile("cp.async.wait_group 1;" ::: "memory")
#define CP_WAIT0()  asm volatile("cp.async.wait_group 0;" ::: "memory")

__device__ __forceinline__ uint32_t f2tf32(float f) {
    uint32_t r;
    asm("cvt.rna.tf32.f32 %0, %1;" : "=r"(r) : "f"(f));
    return r;
}
__device__ __forceinline__ void mma_tf32(float* c, const uint32_t* a, const uint32_t* b) {
    asm volatile(
        "mma.sync.aligned.m16n8k8.row.col.f32.tf32.tf32.f32 "
        "{%0,%1,%2,%3}, {%4,%5,%6,%7}, {%8,%9}, {%0,%1,%2,%3};"
        : "+f"(c[0]), "+f"(c[1]), "+f"(c[2]), "+f"(c[3])
        : "r"(a[0]), "r"(a[1]), "r"(a[2]), "r"(a[3]), "r"(b[0]), "r"(b[1]));
}

// ---------------- GEMM (NT): C[m,n] = alpha * sum_k A[m,k]*B[n,k] ----------------
#define MODE_PLAIN 0
#define MODE_LCA   1   // fused LCA prox epilogue
#define MODE_SCORE 2   // skip tiles fully above the causal diagonal
#define MODE_PV    3   // causal K-limit: kmax = r0+128

#define BK   32
#define STRD 36                       // floats per smem row (144B: 16B-aligned, conflict-free)
#define TILE_SM (128 * STRD)          // floats per tile buffer
#define GSMEM_BYTES (4 * TILE_SM * 4) // 2 A buffers + 2 B buffers = 73728 B

template <int MODE>
__global__ void __launch_bounds__(256, 2)
mm_tf32(const float* __restrict__ A, const float* __restrict__ Bm, float* __restrict__ C,
        int K, int ldA, int ldB, int ldC, float alpha,
        long sA, long sB, long sC,
        const float* __restrict__ U, float* __restrict__ Vst,
        const float* __restrict__ loglam)
{
    const int r0 = blockIdx.y * 128;
    const int c0 = blockIdx.x * 128;
    if (MODE == MODE_SCORE && c0 >= r0 + 128) return;   // fully masked tile

    A  += blockIdx.z * sA;
    Bm += blockIdx.z * sB;
    C  += blockIdx.z * sC;

    extern __shared__ float sm[];
    float* Asb[2] = { sm,               sm + TILE_SM };
    float* Bsb[2] = { sm + 2 * TILE_SM, sm + 3 * TILE_SM };

    const int tid  = threadIdx.x;
    const int lane = tid & 31;
    const int wid  = tid >> 5;
    const int wm   = (wid >> 2) * 64;   // warp row offset in tile
    const int wn   = (wid & 3) * 32;    // warp col offset in tile
    const int lr   = lane >> 2;         // 0..7
    const int lc   = lane & 3;          // 0..3

    const int kmax = (MODE == MODE_PV) ? min(K, r0 + 128) : K;
    const int nch  = kmax / BK;

    float acc[4][4][4];
#pragma unroll
    for (int i = 0; i < 4; i++)
#pragma unroll
        for (int j = 0; j < 4; j++)
#pragma unroll
            for (int e = 0; e < 4; e++) acc[i][j][e] = 0.f;

    // async stage chunk c into buffer c&1
    auto issue = [&](int c) {
        const int buf = c & 1;
        const float* Ac = A  + (long)r0 * ldA + c * BK;
        const float* Bc = Bm + (long)c0 * ldB + c * BK;
        const uint32_t ab = smem_u32(Asb[buf]);
        const uint32_t bb = smem_u32(Bsb[buf]);
#pragma unroll
        for (int i = 0; i < 4; i++) {
            const int idx = tid + i * 256;       // 1024 16B chunks per tile
            const int row = idx >> 3, c4 = idx & 7;
            cp_async16(ab + (uint32_t)(row * STRD + c4 * 4) * 4, Ac + (long)row * ldA + c4 * 4);
            cp_async16(bb + (uint32_t)(row * STRD + c4 * 4) * 4, Bc + (long)row * ldB + c4 * 4);
        }
        CP_COMMIT();
    };

    issue(0);
    for (int c = 0; c < nch; c++) {
        if (c + 1 < nch) { issue(c + 1); CP_WAIT1(); }
        else             { CP_WAIT0(); }
        __syncthreads();

        const float* Ab = Asb[c & 1];
        const float* Bb = Bsb[c & 1];
#pragma unroll
        for (int o = 0; o < 4; o++) {            // 4 k-octets per chunk
            const int kb = o * 8;
            uint32_t af[4][4], bf[4][2];
#pragma unroll
            for (int mt = 0; mt < 4; mt++) {
                const float* p  = Ab + (wm + mt * 16 + lr) * STRD + kb + lc;
                const float* p2 = p + 8 * STRD;
                af[mt][0] = f2tf32(p[0]);  af[mt][1] = f2tf32(p2[0]);
                af[mt][2] = f2tf32(p[4]);  af[mt][3] = f2tf32(p2[4]);
            }
#pragma unroll
            for (int nt = 0; nt < 4; nt++) {
                const float* p = Bb + (wn + nt * 8 + lr) * STRD + kb + lc;
                bf[nt][0] = f2tf32(p[0]);  bf[nt][1] = f2tf32(p[4]);
            }
#pragma unroll
            for (int mt = 0; mt < 4; mt++)
#pragma unroll
                for (int nt = 0; nt < 4; nt++)
                    mma_tf32(acc[mt][nt], af[mt], bf[nt]);
        }
        __syncthreads();
    }

    // ---------------- epilogue ----------------
    const float lam = (MODE == MODE_LCA) ? expf(*loglam) : 0.f;
#pragma unroll
    for (int mt = 0; mt < 4; mt++) {
#pragma unroll
        for (int h = 0; h < 2; h++) {
            const int row = r0 + wm + mt * 16 + lr + h * 8;
#pragma unroll
            for (int nt = 0; nt < 4; nt++) {
                const int col = c0 + wn + nt * 8 + lc * 2;
                const long idx = (long)row * ldC + col;
                float x0 = acc[mt][nt][h * 2 + 0];
                float x1 = acc[mt][nt][h * 2 + 1];
                if (MODE == MODE_LCA) {
                    float2 u2 = *(const float2*)(U + idx);
                    float2 v2 = *(const float2*)(Vst + idx);
                    float2 vn, o2;
                    vn.x = v2.x + ETA_C * (u2.x - v2.x - x0);
                    vn.y = v2.y + ETA_C * (u2.y - v2.y - x1);
                    *(float2*)(Vst + idx) = vn;
                    float s;
                    s = fabsf(vn.x) - lam; o2.x = (s > 0.f) ? copysignf(s, vn.x) : 0.f;
                    s = fabsf(vn.y) - lam; o2.y = (s > 0.f) ? copysignf(s, vn.y) : 0.f;
                    *(float2*)(C + idx) = o2;
                } else {
                    float2 o2 = make_float2(alpha * x0, alpha * x1);
                    *(float2*)(C + idx) = o2;
                }
            }
        }
    }
}

// ---------------- small kernels ----------------
__global__ void symzero(const float* __restrict__ G, float* __restrict__ Gs)
{
    const long idx = (long)blockIdx.x * blockDim.x + threadIdx.x;
    if (idx >= (long)D_SZ * D_SZ) return;
    const int i = (int)(idx / D_SZ), j = (int)(idx % D_SZ);
    Gs[idx] = (i == j) ? 0.f : 0.5f * (G[idx] + G[(long)j * D_SZ + i]);
}

__global__ void lca_init(const float* __restrict__ U, float* __restrict__ Vst,
                         float* __restrict__ Aout, const float* __restrict__ loglam)
{
    const long idx = (long)blockIdx.x * blockDim.x + threadIdx.x;
    const float lam = expf(*loglam);
    const float vn = ETA_C * U[idx];
    Vst[idx] = vn;
    const float s = fabsf(vn) - lam;
    Aout[idx] = (s > 0.f) ? copysignf(s, vn) : 0.f;
}

// V [B][T][D] -> Vt [B][D][T]
__global__ void transpose_bt(const float* __restrict__ in, float* __restrict__ out)
{
    __shared__ float t[32][33];
    const int b = blockIdx.z;
    const int t0 = blockIdx.x * 32, d0 = blockIdx.y * 32;
    in  += (long)b * T_SZ * D_SZ;
    out += (long)b * T_SZ * D_SZ;
    const int x = threadIdx.x, y = threadIdx.y;
#pragma unroll
    for (int i = 0; i < 32; i += 8)
        t[y + i][x] = in[(long)(t0 + y + i) * D_SZ + d0 + x];
    __syncthreads();
#pragma unroll
    for (int i = 0; i < 32; i += 8)
        out[(long)(d0 + y + i) * T_SZ + t0 + x] = t[x][y + i];
}

__global__ void softmax_causal(float* __restrict__ S)
{
    const int i = blockIdx.x;
    const int b = blockIdx.y;
    float* row = S + ((long)b * T_SZ + i) * T_SZ;
    const int tid = threadIdx.x;
    const int n = i + 1;
    __shared__ float red[256];

    float mx = -INFINITY;
    for (int j = tid; j < n; j += 256) mx = fmaxf(mx, row[j]);
    red[tid] = mx;
    __syncthreads();
    for (int s = 128; s > 0; s >>= 1) {
        if (tid < s) red[tid] = fmaxf(red[tid], red[tid + s]);
        __syncthreads();
    }
    mx = red[0];
    __syncthreads();

    float sum = 0.f;
    for (int j = tid; j < n; j += 256) {
        float e = expf(row[j] - mx);
        row[j] = e;
        sum += e;
    }
    red[tid] = sum;
    __syncthreads();
    for (int s = 128; s > 0; s >>= 1) {
        if (tid < s) red[tid] += red[tid + s];
        __syncthreads();
    }
    const float inv = 1.f / red[0];
    for (int j = tid; j < n; j += 256) row[j] *= inv;
    for (int j = n + tid; j < T_SZ; j += 256) row[j] = 0.f;
}

// ---------------- launch ----------------
extern "C" void kernel_launch(void* const* d_in, const int* in_sizes, int n_in,
                              void* d_out, int out_size)
{
    const float* x        = (const float*)d_in[0];
    const float* W_qkv    = (const float*)d_in[1];
    const float* W_out    = (const float*)d_in[2];
    const float* Gq_raw   = (const float*)d_in[3];
    const float* loglam_q = (const float*)d_in[4];
    const float* Gk_raw   = (const float*)d_in[5];
    const float* loglam_k = (const float*)d_in[6];
    float* out = (float*)d_out;
    (void)in_sizes; (void)n_in; (void)out_size;

    float *uq, *uk, *vv, *vt, *vq, *vk, *aqb, *akb, *Gq, *Gk, *S, *o;
    cudaGetSymbolAddress((void**)&uq,  g_uq);
    cudaGetSymbolAddress((void**)&uk,  g_uk);
    cudaGetSymbolAddress((void**)&vv,  g_vv);
    cudaGetSymbolAddress((void**)&vt,  g_vt);
    cudaGetSymbolAddress((void**)&vq,  g_vq);
    cudaGetSymbolAddress((void**)&vk,  g_vk);
    cudaGetSymbolAddress((void**)&aqb, g_aq);
    cudaGetSymbolAddress((void**)&akb, g_ak);
    cudaGetSymbolAddress((void**)&Gq,  g_Gq);
    cudaGetSymbolAddress((void**)&Gk,  g_Gk);
    cudaGetSymbolAddress((void**)&S,   g_S);
    cudaGetSymbolAddress((void**)&o,   g_o);

    cudaFuncSetAttribute(mm_tf32<MODE_PLAIN>, cudaFuncAttributeMaxDynamicSharedMemorySize, GSMEM_BYTES);
    cudaFuncSetAttribute(mm_tf32<MODE_LCA>,   cudaFuncAttributeMaxDynamicSharedMemorySize, GSMEM_BYTES);
    cudaFuncSetAttribute(mm_tf32<MODE_SCORE>, cudaFuncAttributeMaxDynamicSharedMemorySize, GSMEM_BYTES);
    cudaFuncSetAttribute(mm_tf32<MODE_PV>,    cudaFuncAttributeMaxDynamicSharedMemorySize, GSMEM_BYTES);

    float* aq[2] = { aqb, aqb + (long)M_SZ * D_SZ };
    float* ak[2] = { akb, akb + (long)M_SZ * D_SZ };

    const dim3 thr(256);
    const long MD = (long)M_SZ * D_SZ;
    const long TD = (long)T_SZ * D_SZ;
    const long TT = (long)T_SZ * T_SZ;

    // 1) symmetrize + zero-diag G
    {
        dim3 g((D_SZ * D_SZ + 255) / 256);
        symzero<<<g, thr>>>(Gq_raw, Gq);
        symzero<<<g, thr>>>(Gk_raw, Gk);
    }

    // 2) QKV projections (NT): M=8192, N=1024, K=1024
    {
        dim3 g(D_SZ / 128, M_SZ / 128, 1);
        mm_tf32<MODE_PLAIN><<<g, thr, GSMEM_BYTES>>>(x, W_qkv,                         uq, D_SZ, D_SZ, D_SZ, D_SZ, 1.f, 0, 0, 0, nullptr, nullptr, nullptr);
        mm_tf32<MODE_PLAIN><<<g, thr, GSMEM_BYTES>>>(x, W_qkv + (long)D_SZ * D_SZ,     uk, D_SZ, D_SZ, D_SZ, D_SZ, 1.f, 0, 0, 0, nullptr, nullptr, nullptr);
        mm_tf32<MODE_PLAIN><<<g, thr, GSMEM_BYTES>>>(x, W_qkv + (long)2 * D_SZ * D_SZ, vv, D_SZ, D_SZ, D_SZ, D_SZ, 1.f, 0, 0, 0, nullptr, nullptr, nullptr);
    }

    // 3) transpose V for the NT P@V GEMM
    {
        dim3 g(T_SZ / 32, D_SZ / 32, B_SZ);
        transpose_bt<<<g, dim3(32, 8)>>>(vv, vt);
    }

    // 4) LCA iteration 1 (elementwise)
    {
        dim3 g((unsigned)(MD / 256));
        lca_init<<<g, thr>>>(uq, vq, aq[0], loglam_q);
        lca_init<<<g, thr>>>(uk, vk, ak[0], loglam_k);
    }

    // 5) LCA iterations 2..10: fused a@G + prox (G symmetric -> NT)
    {
        dim3 g(D_SZ / 128, M_SZ / 128, 1);
        int cur = 0;
        for (int it = 0; it < LCA_GEMM_ITERS; it++) {
            mm_tf32<MODE_LCA><<<g, thr, GSMEM_BYTES>>>(aq[cur], Gq, aq[cur ^ 1], D_SZ, D_SZ, D_SZ, D_SZ, 1.f,
                                                       0, 0, 0, uq, vq, loglam_q);
            mm_tf32<MODE_LCA><<<g, thr, GSMEM_BYTES>>>(ak[cur], Gk, ak[cur ^ 1], D_SZ, D_SZ, D_SZ, D_SZ, 1.f,
                                                       0, 0, 0, uk, vk, loglam_k);
            cur ^= 1;
        }
    }
    float* qf = aq[1];
    float* kf = ak[1];

    // 6) scores S = q k^T / 32, causal tiles skipped, batched over z
    {
        dim3 g(T_SZ / 128, T_SZ / 128, B_SZ);
        mm_tf32<MODE_SCORE><<<g, thr, GSMEM_BYTES>>>(qf, kf, S, D_SZ, D_SZ, D_SZ, T_SZ, 0.03125f,
                                                     TD, TD, TT, nullptr, nullptr, nullptr);
    }

    // 7) causal softmax (in place; zeroes the masked tail)
    {
        dim3 g(T_SZ, B_SZ);
        softmax_causal<<<g, thr>>>(S);
    }

    // 8) o = P @ V  (NT against Vt, causal K-limit), batched
    {
        dim3 g(D_SZ / 128, T_SZ / 128, B_SZ);
        mm_tf32<MODE_PV><<<g, thr, GSMEM_BYTES>>>(S, vt, o, T_SZ, T_SZ, T_SZ, D_SZ, 1.f,
                                                  TT, TD, TD, nullptr, nullptr, nullptr);
    }

    // 9) out = o @ W_out^T
    {
        dim3 g(D_SZ / 128, M_SZ / 128, 1);
        mm_tf32<MODE_PLAIN><<<g, thr, GSMEM_BYTES>>>(o, W_out, out, D_SZ, D_SZ, D_SZ, D_SZ, 1.f,
                                                     0, 0, 0, nullptr, nullptr, nullptr);
    }
}

// round 4
// speedup vs baseline: 3.8850x; 1.2856x over previous
#include <cuda_runtime.h>
#include <cstdint>
#include <math.h>

// ---------------- problem constants ----------------
#define B_SZ 4
#define T_SZ 2048
#define D_SZ 1024
#define M_SZ (B_SZ * T_SZ)
#define MD   ((long)M_SZ * D_SZ)
#define DD   ((long)D_SZ * D_SZ)
#define ETA_C 0.1f
#define LCA_GEMM_ITERS 9   // iteration 1 is elementwise (a=0, v=0)

// ---------------- scratch (device globals; no allocation) ----------------
__device__ float g_u3[3 * M_SZ * D_SZ];      // u_q, u_k, v (contiguous, z-indexed)
__device__ float g_vt[M_SZ * D_SZ];          // V transposed per batch: [B][D][T]
__device__ float g_vs[2 * M_SZ * D_SZ];      // LCA v-state (q, k)
__device__ float g_ab[2][2 * M_SZ * D_SZ];   // LCA codes ping-pong x (q,k)
__device__ float g_G2[2 * D_SZ * D_SZ];      // symmetrized zero-diag Gq, Gk
__device__ float g_S[(size_t)B_SZ * T_SZ * T_SZ];
__device__ float g_o[M_SZ * D_SZ];

// ---------------- helpers ----------------
__device__ __forceinline__ uint32_t smem_u32(const void* p) {
    uint32_t a;
    asm("{ .reg .u64 t; cvta.to.shared.u64 t, %1; cvt.u32.u64 %0, t; }" : "=r"(a) : "l"(p));
    return a;
}
__device__ __forceinline__ void cp_async16(uint32_t dst, const void* src) {
    asm volatile("cp.async.cg.shared.global [%0], [%1], 16;" :: "r"(dst), "l"(src));
}
#define CP_COMMIT() asm volatile("cp.async.commit_group;" ::: "memory")
#define CP_WAIT1()  asm volatile("cp.async.wait_group 1;" ::: "memory")
#define CP_WAIT0()  asm volatile("cp.async.wait_group 0;" ::: "memory")

__device__ __forceinline__ uint32_t f2tf32(float f) {
    uint32_t r;
    asm("cvt.rna.tf32.f32 %0, %1;" : "=r"(r) : "f"(f));
    return r;
}
__device__ __forceinline__ void mma_tf32(float* c, const uint32_t* a, const uint32_t* b) {
    asm volatile(
        "mma.sync.aligned.m16n8k8.row.col.f32.tf32.tf32.f32 "
        "{%0,%1,%2,%3}, {%4,%5,%6,%7}, {%8,%9}, {%0,%1,%2,%3};"
        : "+f"(c[0]), "+f"(c[1]), "+f"(c[2]), "+f"(c[3])
        : "r"(a[0]), "r"(a[1]), "r"(a[2]), "r"(a[3]), "r"(b[0]), "r"(b[1]));
}

// ---------------- GEMM (NT): C[m,n] = alpha * sum_k A[m,k]*B[n,k] ----------------
// k-columns within each 32-K chunk are PERMUTED consistently for A and B:
// mma-k (octet o, lane-k lc)      -> smem col 8o + 2lc
// mma-k (octet o, lane-k lc + 4)  -> smem col 8o + 2lc + 1
// (sum over k is permutation-invariant; enables float2 fragment loads)
#define MODE_PLAIN 0
#define MODE_LCA   1   // fused LCA prox epilogue (z: 0=q, 1=k)
#define MODE_SCORE 2   // skip tiles fully above the causal diagonal
#define MODE_PV    3   // causal K-limit: kmax = r0+128

#define BK   32
#define STRD 40                       // floats per smem row (160B; LDS.64 conflict-free)
#define TILE_SM (128 * STRD)          // floats per tile buffer
#define GSMEM_BYTES (4 * TILE_SM * 4) // 2 A + 2 B buffers = 81920 B

template <int MODE>
__global__ void __launch_bounds__(256, 2)
mm_tf32(const float* __restrict__ A, const float* __restrict__ Bm, float* __restrict__ C,
        int K, int ldA, int ldB, int ldC, float alpha,
        long sA, long sB, long sC,
        const float* __restrict__ U, float* __restrict__ Vst,
        const float* __restrict__ llq, const float* __restrict__ llk)
{
    const int r0 = blockIdx.y * 128;
    const int c0 = blockIdx.x * 128;
    if (MODE == MODE_SCORE && c0 >= r0 + 128) return;   // fully masked tile

    const long bz = blockIdx.z;
    A  += bz * sA;
    Bm += bz * sB;
    C  += bz * sC;

    extern __shared__ float sm[];
    float* Asb[2] = { sm,               sm + TILE_SM };
    float* Bsb[2] = { sm + 2 * TILE_SM, sm + 3 * TILE_SM };

    const int tid  = threadIdx.x;
    const int lane = tid & 31;
    const int wid  = tid >> 5;
    const int wm   = (wid >> 2) * 64;   // warp row offset
    const int wn   = (wid & 3) * 32;    // warp col offset
    const int lr   = lane >> 2;         // 0..7
    const int lc   = lane & 3;          // 0..3

    const int kmax = (MODE == MODE_PV) ? min(K, r0 + 128) : K;
    const int nch  = kmax / BK;

    float acc[4][4][4];
#pragma unroll
    for (int i = 0; i < 4; i++)
#pragma unroll
        for (int j = 0; j < 4; j++)
#pragma unroll
            for (int e = 0; e < 4; e++) acc[i][j][e] = 0.f;

    auto issue = [&](int c) {
        const int buf = c & 1;
        const float* Ac = A  + (long)r0 * ldA + c * BK;
        const float* Bc = Bm + (long)c0 * ldB + c * BK;
        const uint32_t ab = smem_u32(Asb[buf]);
        const uint32_t bb = smem_u32(Bsb[buf]);
#pragma unroll
        for (int i = 0; i < 4; i++) {
            const int idx = tid + i * 256;       // 1024 16B chunks per tile
            const int row = idx >> 3, c4 = idx & 7;
            cp_async16(ab + (uint32_t)(row * STRD + c4 * 4) * 4, Ac + (long)row * ldA + c4 * 4);
            cp_async16(bb + (uint32_t)(row * STRD + c4 * 4) * 4, Bc + (long)row * ldB + c4 * 4);
        }
        CP_COMMIT();
    };

    issue(0);
    for (int c = 0; c < nch; c++) {
        if (c + 1 < nch) { issue(c + 1); CP_WAIT1(); }
        else             { CP_WAIT0(); }
        __syncthreads();

        const float* Ab = Asb[c & 1];
        const float* Bb = Bsb[c & 1];
#pragma unroll
        for (int o = 0; o < 4; o++) {            // 4 k-octets per chunk
            const int koff = o * 8 + lc * 2;     // permuted k-column pair
            uint32_t af[4][4], bf[4][2];
#pragma unroll
            for (int mt = 0; mt < 4; mt++) {
                const float2 lo = *(const float2*)(Ab + (wm + mt * 16 + lr) * STRD + koff);
                const float2 hi = *(const float2*)(Ab + (wm + mt * 16 + lr + 8) * STRD + koff);
                af[mt][0] = f2tf32(lo.x);  af[mt][2] = f2tf32(lo.y);
                af[mt][1] = f2tf32(hi.x);  af[mt][3] = f2tf32(hi.y);
            }
#pragma unroll
            for (int nt = 0; nt < 4; nt++) {
                const float2 bv = *(const float2*)(Bb + (wn + nt * 8 + lr) * STRD + koff);
                bf[nt][0] = f2tf32(bv.x);  bf[nt][1] = f2tf32(bv.y);
            }
#pragma unroll
            for (int mt = 0; mt < 4; mt++)
#pragma unroll
                for (int nt = 0; nt < 4; nt++)
                    mma_tf32(acc[mt][nt], af[mt], bf[nt]);
        }
        __syncthreads();
    }

    // ---------------- epilogue ----------------
    const float lam = (MODE == MODE_LCA) ? expf(bz == 0 ? *llq : *llk) : 0.f;
#pragma unroll
    for (int mt = 0; mt < 4; mt++) {
#pragma unroll
        for (int h = 0; h < 2; h++) {
            const int row = r0 + wm + mt * 16 + lr + h * 8;
#pragma unroll
            for (int nt = 0; nt < 4; nt++) {
                const int col = c0 + wn + nt * 8 + lc * 2;
                const long idx = (long)row * ldC + col;
                float x0 = acc[mt][nt][h * 2 + 0];
                float x1 = acc[mt][nt][h * 2 + 1];
                if (MODE == MODE_LCA) {
                    float2 u2 = *(const float2*)(U + bz * sC + idx);
                    float2 v2 = *(const float2*)(Vst + bz * sC + idx);
                    float2 vn, o2;
                    vn.x = v2.x + ETA_C * (u2.x - v2.x - x0);
                    vn.y = v2.y + ETA_C * (u2.y - v2.y - x1);
                    *(float2*)(Vst + bz * sC + idx) = vn;
                    float s;
                    s = fabsf(vn.x) - lam; o2.x = (s > 0.f) ? copysignf(s, vn.x) : 0.f;
                    s = fabsf(vn.y) - lam; o2.y = (s > 0.f) ? copysignf(s, vn.y) : 0.f;
                    *(float2*)(C + idx) = o2;
                } else {
                    *(float2*)(C + idx) = make_float2(alpha * x0, alpha * x1);
                }
            }
        }
    }
}

// ---------------- small kernels ----------------
__global__ void symzero(const float* __restrict__ G, float* __restrict__ Gs)
{
    const long idx = (long)blockIdx.x * blockDim.x + threadIdx.x;
    if (idx >= DD) return;
    const int i = (int)(idx / D_SZ), j = (int)(idx % D_SZ);
    Gs[idx] = (i == j) ? 0.f : 0.5f * (G[idx] + G[(long)j * D_SZ + i]);
}

// both q and k halves in one launch
__global__ void lca_init(const float* __restrict__ U, float* __restrict__ Vst,
                         float* __restrict__ Aout,
                         const float* __restrict__ llq, const float* __restrict__ llk)
{
    const long idx = (long)blockIdx.x * blockDim.x + threadIdx.x;
    const float lam = expf(idx < MD ? *llq : *llk);
    const float vn = ETA_C * U[idx];
    Vst[idx] = vn;
    const float s = fabsf(vn) - lam;
    Aout[idx] = (s > 0.f) ? copysignf(s, vn) : 0.f;
}

// V [B][T][D] -> Vt [B][D][T]
__global__ void transpose_bt(const float* __restrict__ in, float* __restrict__ out)
{
    __shared__ float t[32][33];
    const int b = blockIdx.z;
    const int t0 = blockIdx.x * 32, d0 = blockIdx.y * 32;
    in  += (long)b * T_SZ * D_SZ;
    out += (long)b * T_SZ * D_SZ;
    const int x = threadIdx.x, y = threadIdx.y;
#pragma unroll
    for (int i = 0; i < 32; i += 8)
        t[y + i][x] = in[(long)(t0 + y + i) * D_SZ + d0 + x];
    __syncthreads();
#pragma unroll
    for (int i = 0; i < 32; i += 8)
        out[(long)(d0 + y + i) * T_SZ + t0 + x] = t[x][y + i];
}

__global__ void softmax_causal(float* __restrict__ S)
{
    const int i = blockIdx.x;
    const int b = blockIdx.y;
    float* row = S + ((long)b * T_SZ + i) * T_SZ;
    const int tid = threadIdx.x;
    const int n = i + 1;
    __shared__ float red[256];

    float mx = -INFINITY;
    for (int j = tid; j < n; j += 256) mx = fmaxf(mx, row[j]);
    red[tid] = mx;
    __syncthreads();
    for (int s = 128; s > 0; s >>= 1) {
        if (tid < s) red[tid] = fmaxf(red[tid], red[tid + s]);
        __syncthreads();
    }
    mx = red[0];
    __syncthreads();

    float sum = 0.f;
    for (int j = tid; j < n; j += 256) {
        float e = expf(row[j] - mx);
        row[j] = e;
        sum += e;
    }
    red[tid] = sum;
    __syncthreads();
    for (int s = 128; s > 0; s >>= 1) {
        if (tid < s) red[tid] += red[tid + s];
        __syncthreads();
    }
    const float inv = 1.f / red[0];
    for (int j = tid; j < n; j += 256) row[j] *= inv;
    for (int j = n + tid; j < T_SZ; j += 256) row[j] = 0.f;
}

// ---------------- launch ----------------
extern "C" void kernel_launch(void* const* d_in, const int* in_sizes, int n_in,
                              void* d_out, int out_size)
{
    const float* x        = (const float*)d_in[0];
    const float* W_qkv    = (const float*)d_in[1];
    const float* W_out    = (const float*)d_in[2];
    const float* Gq_raw   = (const float*)d_in[3];
    const float* loglam_q = (const float*)d_in[4];
    const float* Gk_raw   = (const float*)d_in[5];
    const float* loglam_k = (const float*)d_in[6];
    float* out = (float*)d_out;
    (void)in_sizes; (void)n_in; (void)out_size;

    float *u3, *vt, *vs, *abb, *G2, *S, *o;
    cudaGetSymbolAddress((void**)&u3,  g_u3);
    cudaGetSymbolAddress((void**)&vt,  g_vt);
    cudaGetSymbolAddress((void**)&vs,  g_vs);
    cudaGetSymbolAddress((void**)&abb, g_ab);
    cudaGetSymbolAddress((void**)&G2,  g_G2);
    cudaGetSymbolAddress((void**)&S,   g_S);
    cudaGetSymbolAddress((void**)&o,   g_o);

    cudaFuncSetAttribute(mm_tf32<MODE_PLAIN>, cudaFuncAttributeMaxDynamicSharedMemorySize, GSMEM_BYTES);
    cudaFuncSetAttribute(mm_tf32<MODE_LCA>,   cudaFuncAttributeMaxDynamicSharedMemorySize, GSMEM_BYTES);
    cudaFuncSetAttribute(mm_tf32<MODE_SCORE>, cudaFuncAttributeMaxDynamicSharedMemorySize, GSMEM_BYTES);
    cudaFuncSetAttribute(mm_tf32<MODE_PV>,    cudaFuncAttributeMaxDynamicSharedMemorySize, GSMEM_BYTES);

    float* ab[2] = { abb, abb + 2 * MD };   // ping-pong, each holding q then k
    float* vvv = u3 + 2 * MD;               // attention values live in slot 2

    const dim3 thr(256);
    const long TD = (long)T_SZ * D_SZ;
    const long TT = (long)T_SZ * T_SZ;

    // 1) symmetrize + zero-diag G (both)
    {
        dim3 g((unsigned)((DD + 255) / 256));
        symzero<<<g, thr>>>(Gq_raw, G2);
        symzero<<<g, thr>>>(Gk_raw, G2 + DD);
    }

    // 2) QKV projections, single launch (z selects W row-block and output slot)
    {
        dim3 g(D_SZ / 128, M_SZ / 128, 3);
        mm_tf32<MODE_PLAIN><<<g, thr, GSMEM_BYTES>>>(x, W_qkv, u3, D_SZ, D_SZ, D_SZ, D_SZ, 1.f,
                                                     0, DD, MD, nullptr, nullptr, nullptr, nullptr);
    }

    // 3) transpose V for the NT P@V GEMM
    {
        dim3 g(T_SZ / 32, D_SZ / 32, B_SZ);
        transpose_bt<<<g, dim3(32, 8)>>>(vvv, vt);
    }

    // 4) LCA iteration 1 (elementwise, q+k in one launch)
    {
        dim3 g((unsigned)(2 * MD / 256));
        lca_init<<<g, thr>>>(u3, vs, ab[0], loglam_q, loglam_k);
    }

    // 5) LCA iterations 2..10: fused a@G + prox, q+k merged (z)
    {
        dim3 g(D_SZ / 128, M_SZ / 128, 2);
        int cur = 0;
        for (int it = 0; it < LCA_GEMM_ITERS; it++) {
            mm_tf32<MODE_LCA><<<g, thr, GSMEM_BYTES>>>(ab[cur], G2, ab[cur ^ 1],
                                                       D_SZ, D_SZ, D_SZ, D_SZ, 1.f,
                                                       MD, DD, MD, u3, vs, loglam_q, loglam_k);
            cur ^= 1;
        }
        // odd count -> final codes in ab[1]
    }
    float* qf = ab[1];            // q codes
    float* kf = ab[1] + MD;       // k codes

    // 6) scores S = q k^T / 32, causal tiles skipped, batched over z
    {
        dim3 g(T_SZ / 128, T_SZ / 128, B_SZ);
        mm_tf32<MODE_SCORE><<<g, thr, GSMEM_BYTES>>>(qf, kf, S, D_SZ, D_SZ, D_SZ, T_SZ, 0.03125f,
                                                     TD, TD, TT, nullptr, nullptr, nullptr, nullptr);
    }

    // 7) causal softmax (in place; zeroes masked tail)
    {
        dim3 g(T_SZ, B_SZ);
        softmax_causal<<<g, thr>>>(S);
    }

    // 8) o = P @ V  (NT against Vt, causal K-limit), batched
    {
        dim3 g(D_SZ / 128, T_SZ / 128, B_SZ);
        mm_tf32<MODE_PV><<<g, thr, GSMEM_BYTES>>>(S, vt, o, T_SZ, T_SZ, T_SZ, D_SZ, 1.f,
                                                  TT, TD, TD, nullptr, nullptr, nullptr, nullptr);
    }

    // 9) out = o @ W_out^T
    {
        dim3 g(D_SZ / 128, M_SZ / 128, 1);
        mm_tf32<MODE_PLAIN><<<g, thr, GSMEM_BYTES>>>(o, W_out, out, D_SZ, D_SZ, D_SZ, D_SZ, 1.f,
                                                     0, 0, 0, nullptr, nullptr, nullptr, nullptr);
    }
}

// round 5
// speedup vs baseline: 4.4987x; 1.1580x over previous
#include <cuda_runtime.h>
#include <cstdint>
#include <math.h>

// ---------------- problem constants ----------------
#define B_SZ 4
#define T_SZ 2048
#define D_SZ 1024
#define M_SZ (B_SZ * T_SZ)
#define MD   ((long)M_SZ * D_SZ)
#define DD   ((long)D_SZ * D_SZ)
#define ETA_C 0.1f
#define LCA_GEMM_ITERS 9   // iteration 1 is elementwise (a=0, v=0)

// ---------------- scratch (device globals; no allocation) ----------------
__device__ float g_u3[3 * M_SZ * D_SZ];      // u_q, u_k, v (fp32; z-indexed)
__device__ float g_vt[M_SZ * D_SZ];          // V^T per batch [B][D][T] (tf32-rounded)
__device__ float g_vs[2 * M_SZ * D_SZ];      // LCA v-state (fp32)
__device__ float g_ab[2][2 * M_SZ * D_SZ];   // LCA codes ping-pong x (q,k) (tf32-rounded)
__device__ float g_G2[2 * D_SZ * D_SZ];      // sym zero-diag Gq,Gk (tf32-rounded)
__device__ float g_S[(size_t)B_SZ * T_SZ * T_SZ];   // scores / probs
__device__ float g_o[M_SZ * D_SZ];           // attention out (tf32-rounded)
__device__ float g_xr[M_SZ * D_SZ];          // x rounded
__device__ float g_wqkvr[3 * D_SZ * D_SZ];   // W_qkv rounded
__device__ float g_woutr[D_SZ * D_SZ];       // W_out rounded

// ---------------- helpers ----------------
__device__ __forceinline__ uint32_t smem_u32(const void* p) {
    uint32_t a;
    asm("{ .reg .u64 t; cvta.to.shared.u64 t, %1; cvt.u32.u64 %0, t; }" : "=r"(a) : "l"(p));
    return a;
}
__device__ __forceinline__ void cp_async16(uint32_t dst, const void* src) {
    asm volatile("cp.async.cg.shared.global [%0], [%1], 16;" :: "r"(dst), "l"(src));
}
#define CP_COMMIT() asm volatile("cp.async.commit_group;" ::: "memory")
#define CP_WAIT1()  asm volatile("cp.async.wait_group 1;" ::: "memory")
#define CP_WAIT0()  asm volatile("cp.async.wait_group 0;" ::: "memory")

__device__ __forceinline__ uint32_t f2tf32(float f) {
    uint32_t r;
    asm("cvt.rna.tf32.f32 %0, %1;" : "=r"(r) : "f"(f));
    return r;
}
__device__ __forceinline__ float rtf(float f) { return __uint_as_float(f2tf32(f)); }

__device__ __forceinline__ void mma_tf32(float* c, const uint32_t* a, const uint32_t* b) {
    asm volatile(
        "mma.sync.aligned.m16n8k8.row.col.f32.tf32.tf32.f32 "
        "{%0,%1,%2,%3}, {%4,%5,%6,%7}, {%8,%9}, {%0,%1,%2,%3};"
        : "+f"(c[0]), "+f"(c[1]), "+f"(c[2]), "+f"(c[3])
        : "r"(a[0]), "r"(a[1]), "r"(a[2]), "r"(a[3]), "r"(b[0]), "r"(b[1]));
}

// ---------------- GEMM (NT): C[m,n] = alpha * sum_k A[m,k]*B[n,k] ----------------
// ALL inputs are pre-rounded to tf32 by producers; inner loop is LDS+MMA only.
// k-columns within each 32-K chunk are permuted consistently for A and B:
//   mma-k (octet o, lane-k lc)     -> smem col 8o + 2lc
//   mma-k (octet o, lane-k lc + 4) -> smem col 8o + 2lc + 1
#define MODE_PLAIN 0
#define MODE_LCA   1   // fused LCA prox epilogue (z: 0=q, 1=k); writes tf32-rounded a
#define MODE_SCORE 2   // skip tiles fully above the causal diagonal
#define MODE_PV    3   // causal K-limit; writes tf32-rounded C

#define BK   32
#define STRD 40                       // floats per smem row (160B; LDS.64 conflict-free)
#define TILE_SM (128 * STRD)
#define GSMEM_BYTES (4 * TILE_SM * 4) // 2 A + 2 B buffers = 81920 B

template <int MODE>
__global__ void __launch_bounds__(256, 2)
mm_tf32(const float* __restrict__ A, const float* __restrict__ Bm, float* __restrict__ C,
        int K, int ldA, int ldB, int ldC, float alpha,
        long sA, long sB, long sC,
        const float* __restrict__ U, float* __restrict__ Vst,
        const float* __restrict__ llq, const float* __restrict__ llk)
{
    const int r0 = blockIdx.y * 128;
    const int c0 = blockIdx.x * 128;
    if (MODE == MODE_SCORE && c0 >= r0 + 128) return;   // fully masked tile

    const long bz = blockIdx.z;
    A  += bz * sA;
    Bm += bz * sB;
    C  += bz * sC;

    extern __shared__ uint32_t sm[];
    uint32_t* Asb[2] = { sm,               sm + TILE_SM };
    uint32_t* Bsb[2] = { sm + 2 * TILE_SM, sm + 3 * TILE_SM };

    const int tid  = threadIdx.x;
    const int lane = tid & 31;
    const int wid  = tid >> 5;
    const int wm   = (wid >> 2) * 64;
    const int wn   = (wid & 3) * 32;
    const int lr   = lane >> 2;         // 0..7
    const int lc   = lane & 3;          // 0..3

    const int kmax = (MODE == MODE_PV) ? min(K, r0 + 128) : K;
    const int nch  = kmax / BK;

    float acc[4][4][4];
#pragma unroll
    for (int i = 0; i < 4; i++)
#pragma unroll
        for (int j = 0; j < 4; j++)
#pragma unroll
            for (int e = 0; e < 4; e++) acc[i][j][e] = 0.f;

    auto issue = [&](int c) {
        const int buf = c & 1;
        const float* Ac = A  + (long)r0 * ldA + c * BK;
        const float* Bc = Bm + (long)c0 * ldB + c * BK;
        const uint32_t ab = smem_u32(Asb[buf]);
        const uint32_t bb = smem_u32(Bsb[buf]);
#pragma unroll
        for (int i = 0; i < 4; i++) {
            const int idx = tid + i * 256;
            const int row = idx >> 3, c4 = idx & 7;
            cp_async16(ab + (uint32_t)(row * STRD + c4 * 4) * 4, Ac + (long)row * ldA + c4 * 4);
            cp_async16(bb + (uint32_t)(row * STRD + c4 * 4) * 4, Bc + (long)row * ldB + c4 * 4);
        }
        CP_COMMIT();
    };

    issue(0);
    for (int c = 0; c < nch; c++) {
        if (c + 1 < nch) { issue(c + 1); CP_WAIT1(); }
        else             { CP_WAIT0(); }
        __syncthreads();

        const uint32_t* Ab = Asb[c & 1];
        const uint32_t* Bb = Bsb[c & 1];
#pragma unroll
        for (int o = 0; o < 4; o++) {
            const int koff = o * 8 + lc * 2;
            uint32_t af[4][4], bf[4][2];
#pragma unroll
            for (int mt = 0; mt < 4; mt++) {
                const uint2 lo = *(const uint2*)(Ab + (wm + mt * 16 + lr) * STRD + koff);
                const uint2 hi = *(const uint2*)(Ab + (wm + mt * 16 + lr + 8) * STRD + koff);
                af[mt][0] = lo.x;  af[mt][2] = lo.y;
                af[mt][1] = hi.x;  af[mt][3] = hi.y;
            }
#pragma unroll
            for (int nt = 0; nt < 4; nt++) {
                const uint2 bv = *(const uint2*)(Bb + (wn + nt * 8 + lr) * STRD + koff);
                bf[nt][0] = bv.x;  bf[nt][1] = bv.y;
            }
#pragma unroll
            for (int mt = 0; mt < 4; mt++)
#pragma unroll
                for (int nt = 0; nt < 4; nt++)
                    mma_tf32(acc[mt][nt], af[mt], bf[nt]);
        }
        __syncthreads();
    }

    // ---------------- epilogue ----------------
    const float lam = (MODE == MODE_LCA) ? expf(bz == 0 ? *llq : *llk) : 0.f;
#pragma unroll
    for (int mt = 0; mt < 4; mt++) {
#pragma unroll
        for (int h = 0; h < 2; h++) {
            const int row = r0 + wm + mt * 16 + lr + h * 8;
#pragma unroll
            for (int nt = 0; nt < 4; nt++) {
                const int col = c0 + wn + nt * 8 + lc * 2;
                const long idx = (long)row * ldC + col;
                float x0 = acc[mt][nt][h * 2 + 0];
                float x1 = acc[mt][nt][h * 2 + 1];
                if (MODE == MODE_LCA) {
                    float2 u2 = *(const float2*)(U + bz * sC + idx);
                    float2 v2 = *(const float2*)(Vst + bz * sC + idx);
                    float2 vn, o2;
                    vn.x = v2.x + ETA_C * (u2.x - v2.x - x0);
                    vn.y = v2.y + ETA_C * (u2.y - v2.y - x1);
                    *(float2*)(Vst + bz * sC + idx) = vn;
                    float s;
                    s = fabsf(vn.x) - lam; o2.x = (s > 0.f) ? rtf(copysignf(s, vn.x)) : 0.f;
                    s = fabsf(vn.y) - lam; o2.y = (s > 0.f) ? rtf(copysignf(s, vn.y)) : 0.f;
                    *(float2*)(C + idx) = o2;
                } else if (MODE == MODE_PV) {
                    *(float2*)(C + idx) = make_float2(rtf(x0), rtf(x1));   // feeds final GEMM
                } else {
                    *(float2*)(C + idx) = make_float2(alpha * x0, alpha * x1);
                }
            }
        }
    }
}

// ---------------- small kernels ----------------
// tf32 round-copy (float4 vectorized; n divisible by 1024)
__global__ void round_copy(const float* __restrict__ in, float* __restrict__ out)
{
    const long i = ((long)blockIdx.x * blockDim.x + threadIdx.x) * 4;
    float4 v = *(const float4*)(in + i);
    v.x = rtf(v.x); v.y = rtf(v.y); v.z = rtf(v.z); v.w = rtf(v.w);
    *(float4*)(out + i) = v;
}

__global__ void symzero(const float* __restrict__ G, float* __restrict__ Gs)
{
    const long idx = (long)blockIdx.x * blockDim.x + threadIdx.x;
    if (idx >= DD) return;
    const int i = (int)(idx / D_SZ), j = (int)(idx % D_SZ);
    Gs[idx] = (i == j) ? 0.f : rtf(0.5f * (G[idx] + G[(long)j * D_SZ + i]));
}

__global__ void lca_init(const float* __restrict__ U, float* __restrict__ Vst,
                         float* __restrict__ Aout,
                         const float* __restrict__ llq, const float* __restrict__ llk)
{
    const long idx = (long)blockIdx.x * blockDim.x + threadIdx.x;
    const float lam = expf(idx < MD ? *llq : *llk);
    const float vn = ETA_C * U[idx];
    Vst[idx] = vn;
    const float s = fabsf(vn) - lam;
    Aout[idx] = (s > 0.f) ? rtf(copysignf(s, vn)) : 0.f;
}

// V [B][T][D] -> Vt [B][D][T], tf32-rounded
__global__ void transpose_bt(const float* __restrict__ in, float* __restrict__ out)
{
    __shared__ float t[32][33];
    const int b = blockIdx.z;
    const int t0 = blockIdx.x * 32, d0 = blockIdx.y * 32;
    in  += (long)b * T_SZ * D_SZ;
    out += (long)b * T_SZ * D_SZ;
    const int x = threadIdx.x, y = threadIdx.y;
#pragma unroll
    for (int i = 0; i < 32; i += 8)
        t[y + i][x] = in[(long)(t0 + y + i) * D_SZ + d0 + x];
    __syncthreads();
#pragma unroll
    for (int i = 0; i < 32; i += 8)
        out[(long)(d0 + y + i) * T_SZ + t0 + x] = rtf(t[x][y + i]);
}

__global__ void softmax_causal(float* __restrict__ S)
{
    const int i = blockIdx.x;
    const int b = blockIdx.y;
    float* row = S + ((long)b * T_SZ + i) * T_SZ;
    const int tid = threadIdx.x;
    const int n = i + 1;
    __shared__ float red[256];

    float mx = -INFINITY;
    for (int j = tid; j < n; j += 256) mx = fmaxf(mx, row[j]);
    red[tid] = mx;
    __syncthreads();
    for (int s = 128; s > 0; s >>= 1) {
        if (tid < s) red[tid] = fmaxf(red[tid], red[tid + s]);
        __syncthreads();
    }
    mx = red[0];
    __syncthreads();

    float sum = 0.f;
    for (int j = tid; j < n; j += 256) {
        float e = expf(row[j] - mx);
        row[j] = e;
        sum += e;
    }
    red[tid] = sum;
    __syncthreads();
    for (int s = 128; s > 0; s >>= 1) {
        if (tid < s) red[tid] += red[tid + s];
        __syncthreads();
    }
    const float inv = 1.f / red[0];
    for (int j = tid; j < n; j += 256) row[j] = rtf(row[j] * inv);   // feeds PV GEMM
    for (int j = n + tid; j < T_SZ; j += 256) row[j] = 0.f;
}

// ---------------- launch ----------------
extern "C" void kernel_launch(void* const* d_in, const int* in_sizes, int n_in,
                              void* d_out, int out_size)
{
    const float* x        = (const float*)d_in[0];
    const float* W_qkv    = (const float*)d_in[1];
    const float* W_out    = (const float*)d_in[2];
    const float* Gq_raw   = (const float*)d_in[3];
    const float* loglam_q = (const float*)d_in[4];
    const float* Gk_raw   = (const float*)d_in[5];
    const float* loglam_k = (const float*)d_in[6];
    float* out = (float*)d_out;
    (void)in_sizes; (void)n_in; (void)out_size;

    float *u3, *vt, *vs, *abb, *G2, *S, *o, *xr, *wqr, *wor;
    cudaGetSymbolAddress((void**)&u3,  g_u3);
    cudaGetSymbolAddress((void**)&vt,  g_vt);
    cudaGetSymbolAddress((void**)&vs,  g_vs);
    cudaGetSymbolAddress((void**)&abb, g_ab);
    cudaGetSymbolAddress((void**)&G2,  g_G2);
    cudaGetSymbolAddress((void**)&S,   g_S);
    cudaGetSymbolAddress((void**)&o,   g_o);
    cudaGetSymbolAddress((void**)&xr,  g_xr);
    cudaGetSymbolAddress((void**)&wqr, g_wqkvr);
    cudaGetSymbolAddress((void**)&wor, g_woutr);

    cudaFuncSetAttribute(mm_tf32<MODE_PLAIN>, cudaFuncAttributeMaxDynamicSharedMemorySize, GSMEM_BYTES);
    cudaFuncSetAttribute(mm_tf32<MODE_LCA>,   cudaFuncAttributeMaxDynamicSharedMemorySize, GSMEM_BYTES);
    cudaFuncSetAttribute(mm_tf32<MODE_SCORE>, cudaFuncAttributeMaxDynamicSharedMemorySize, GSMEM_BYTES);
    cudaFuncSetAttribute(mm_tf32<MODE_PV>,    cudaFuncAttributeMaxDynamicSharedMemorySize, GSMEM_BYTES);

    float* ab[2] = { abb, abb + 2 * MD };
    float* vvv = u3 + 2 * MD;

    const dim3 thr(256);
    const long TD = (long)T_SZ * D_SZ;
    const long TT = (long)T_SZ * T_SZ;

    // 0) pre-round raw GEMM inputs to tf32
    round_copy<<<(unsigned)(MD / 1024), thr>>>(x, xr);
    round_copy<<<(unsigned)(3 * DD / 1024), thr>>>(W_qkv, wqr);
    round_copy<<<(unsigned)(DD / 1024), thr>>>(W_out, wor);

    // 1) symmetrize + zero-diag G (tf32-rounded)
    {
        dim3 g((unsigned)((DD + 255) / 256));
        symzero<<<g, thr>>>(Gq_raw, G2);
        symzero<<<g, thr>>>(Gk_raw, G2 + DD);
    }

    // 2) QKV projections, single launch (z selects W block and output slot); u stays fp32
    {
        dim3 g(D_SZ / 128, M_SZ / 128, 3);
        mm_tf32<MODE_PLAIN><<<g, thr, GSMEM_BYTES>>>(xr, wqr, u3, D_SZ, D_SZ, D_SZ, D_SZ, 1.f,
                                                     0, DD, MD, nullptr, nullptr, nullptr, nullptr);
    }

    // 3) transpose V (tf32-rounded)
    {
        dim3 g(T_SZ / 32, D_SZ / 32, B_SZ);
        transpose_bt<<<g, dim3(32, 8)>>>(vvv, vt);
    }

    // 4) LCA iteration 1 (elementwise, q+k)
    {
        dim3 g((unsigned)(2 * MD / 256));
        lca_init<<<g, thr>>>(u3, vs, ab[0], loglam_q, loglam_k);
    }

    // 5) LCA iterations 2..10: fused a@G + prox, q+k merged over z
    {
        dim3 g(D_SZ / 128, M_SZ / 128, 2);
        int cur = 0;
        for (int it = 0; it < LCA_GEMM_ITERS; it++) {
            mm_tf32<MODE_LCA><<<g, thr, GSMEM_BYTES>>>(ab[cur], G2, ab[cur ^ 1],
                                                       D_SZ, D_SZ, D_SZ, D_SZ, 1.f,
                                                       MD, DD, MD, u3, vs, loglam_q, loglam_k);
            cur ^= 1;
        }
    }
    float* qf = ab[1];
    float* kf = ab[1] + MD;

    // 6) scores S = q k^T / 32, causal tiles skipped
    {
        dim3 g(T_SZ / 128, T_SZ / 128, B_SZ);
        mm_tf32<MODE_SCORE><<<g, thr, GSMEM_BYTES>>>(qf, kf, S, D_SZ, D_SZ, D_SZ, T_SZ, 0.03125f,
                                                     TD, TD, TT, nullptr, nullptr, nullptr, nullptr);
    }

    // 7) causal softmax (in place; rounds probs, zeroes masked tail)
    {
        dim3 g(T_SZ, B_SZ);
        softmax_causal<<<g, thr>>>(S);
    }

    // 8) o = P @ V (NT against Vt, causal K-limit); o tf32-rounded
    {
        dim3 g(D_SZ / 128, T_SZ / 128, B_SZ);
        mm_tf32<MODE_PV><<<g, thr, GSMEM_BYTES>>>(S, vt, o, T_SZ, T_SZ, T_SZ, D_SZ, 1.f,
                                                  TT, TD, TD, nullptr, nullptr, nullptr, nullptr);
    }

    // 9) out = o @ W_out^T (fp32 output)
    {
        dim3 g(D_SZ / 128, M_SZ / 128, 1);
        mm_tf32<MODE_PLAIN><<<g, thr, GSMEM_BYTES>>>(o, wor, out, D_SZ, D_SZ, D_SZ, D_SZ, 1.f,
                                                     0, 0, 0, nullptr, nullptr, nullptr, nullptr);
    }
}